// round 1
// baseline (speedup 1.0000x reference)
#include <cuda_runtime.h>

// Problem constants
#define B_      2
#define N_      100000
#define NPTS    (B_ * N_)          // 200000
#define RES     256
#define RES2    65536
#define CIN_C   64
#define COUT_C  128

// Output layout (concatenated, return order: out, before_pool, x_after, c)
#define OUT_OFF 0
#define BP_OFF  4194304            // 2*128*128*128
#define XA_OFF  20971520           // BP_OFF + 2*128*256*256
#define C_OFF   37748736           // XA_OFF + 2*128*256*256

// ---------------- device scratch (no allocations allowed) ----------------
__device__ float g_h1[(size_t)B_ * COUT_C * RES * RES];   // conv1 output
__device__ float g_xat[(size_t)B_ * RES * RES * COUT_C];  // x_after transposed [b][y][x][c]
__device__ float g_c0[(size_t)NPTS * 128];                // sampled features
__device__ float g_t[(size_t)NPTS * 256];                 // fc1 output
__device__ float g_sums[(size_t)B_ * 128 * RES2];         // scatter sums
__device__ float g_cnt[(size_t)B_ * RES2];                // scatter counts
__device__ int   g_idx[NPTS];                             // per-point bin

// ---------------- zero scratch accumulators ----------------
__global__ void zero_kernel() {
    const size_t ns = (size_t)B_ * 128 * RES2;
    const size_t total = ns + (size_t)B_ * RES2;
    for (size_t i = (size_t)blockIdx.x * blockDim.x + threadIdx.x; i < total;
         i += (size_t)gridDim.x * blockDim.x) {
        if (i < ns) g_sums[i] = 0.f;
        else        g_cnt[i - ns] = 0.f;
    }
}

// ---------------- direct 3x3 conv, register-tiled ----------------
// Block: 256 threads; tile 32x (x) * 8y pixels, 64 output channels.
// Thread: 8 x-contiguous pixels * 8 couts (64 accumulators).
// FUSE: relu first, then add 1x1 conv of x1, write out_std + transposed g_xat.
// !FUSE: relu, write g_h1.
template<int CIN, bool FUSE>
__global__ __launch_bounds__(256, 2)
void conv3x3_kernel(const float* __restrict__ in_param,
                    const float* __restrict__ w,
                    const float* __restrict__ bias,
                    const float* __restrict__ x1,
                    const float* __restrict__ w1,
                    const float* __restrict__ b1,
                    float* __restrict__ out_std)
{
    extern __shared__ float sm[];
    float* s_in = sm;            // [8 ci][10 y][35 (34 used)] = 2800 floats
    float* s_w  = sm + 2800;     // [64 co][8 ci][9 tap]      = 4608 floats

    const int tid = threadIdx.x;
    const int cog = tid >> 5;          // 0..7 (co group)
    const int pix = tid & 31;
    const int xs  = (pix & 3) * 8;     // x strip base 0/8/16/24
    const int ty  = pix >> 2;          // 0..7

    const int bx = blockIdx.x, by = blockIdx.y;
    const int b  = blockIdx.z >> 1;
    const int cb = (blockIdx.z & 1) * 64;

    const float* src = FUSE ? g_h1 : in_param;

    float acc[8][8];
    #pragma unroll
    for (int c = 0; c < 8; c++)
        #pragma unroll
        for (int px = 0; px < 8; px++) acc[c][px] = 0.f;

    const int gy0 = by * 8, gx0 = bx * 32;

    for (int ch = 0; ch < CIN / 8; ch++) {
        __syncthreads();
        // input tile with halo
        for (int e = tid; e < 8 * 10 * 34; e += 256) {
            int ci = e / 340; int r = e - ci * 340;
            int yy = r / 34;  int xx = r - yy * 34;
            int gy = gy0 - 1 + yy, gx = gx0 - 1 + xx;
            float v = 0.f;
            if ((unsigned)gy < 256u && (unsigned)gx < 256u)
                v = src[(((size_t)b * CIN + ch * 8 + ci) * 256 + gy) * 256 + gx];
            s_in[ci * 350 + yy * 35 + xx] = v;
        }
        // weights [64][8][9] (contiguous 72-float runs per co)
        for (int e = tid; e < 64 * 8 * 9; e += 256) {
            int co = e / 72; int r = e - co * 72;
            s_w[e] = w[((size_t)(cb + co) * CIN + ch * 8) * 9 + r];
        }
        __syncthreads();

        #pragma unroll 1
        for (int ci = 0; ci < 8; ci++) {
            #pragma unroll
            for (int ky = 0; ky < 3; ky++) {
                float inrow[10];
                #pragma unroll
                for (int j = 0; j < 10; j++)
                    inrow[j] = s_in[ci * 350 + (ty + ky) * 35 + xs + j];
                #pragma unroll
                for (int kx = 0; kx < 3; kx++) {
                    #pragma unroll
                    for (int c = 0; c < 8; c++) {
                        float wv = s_w[(cog * 8 + c) * 72 + ci * 9 + ky * 3 + kx];
                        #pragma unroll
                        for (int px = 0; px < 8; px++)
                            acc[c][px] = fmaf(inrow[px + kx], wv, acc[c][px]);
                    }
                }
            }
        }
    }

    // bias + relu
    #pragma unroll
    for (int c = 0; c < 8; c++) {
        float bv = bias[cb + cog * 8 + c];
        #pragma unroll
        for (int px = 0; px < 8; px++)
            acc[c][px] = fmaxf(acc[c][px] + bv, 0.f);
    }

    if (FUSE) {
        // += conv1x1(x1) + b1   (after relu, matching reference)
        float* s_in1 = sm;          // [8 ci][8 y][33 (32 used)] = 2112
        float* s_w1  = sm + 2112;   // [64 co][8 ci] = 512
        #pragma unroll
        for (int c = 0; c < 8; c++) {
            float bv = b1[cb + cog * 8 + c];
            #pragma unroll
            for (int px = 0; px < 8; px++) acc[c][px] += bv;
        }
        for (int ch = 0; ch < 64 / 8; ch++) {
            __syncthreads();
            for (int e = tid; e < 8 * 8 * 32; e += 256) {
                int ci = e >> 8; int yy = (e >> 5) & 7; int xx = e & 31;
                s_in1[ci * 264 + yy * 33 + xx] =
                    x1[(((size_t)b * 64 + ch * 8 + ci) * 256 + gy0 + yy) * 256 + gx0 + xx];
            }
            for (int e = tid; e < 512; e += 256)
                s_w1[e] = w1[(size_t)(cb + (e >> 3)) * 64 + ch * 8 + (e & 7)];
            __syncthreads();
            #pragma unroll 1
            for (int ci = 0; ci < 8; ci++) {
                float inv[8];
                #pragma unroll
                for (int j = 0; j < 8; j++)
                    inv[j] = s_in1[ci * 264 + ty * 33 + xs + j];
                #pragma unroll
                for (int c = 0; c < 8; c++) {
                    float wv = s_w1[(cog * 8 + c) * 8 + ci];
                    #pragma unroll
                    for (int px = 0; px < 8; px++)
                        acc[c][px] = fmaf(inv[px], wv, acc[c][px]);
                }
            }
        }
    }

    // write standard [b][co][y][x] layout
    const int gy = gy0 + ty;
    float* dst_base = FUSE ? out_std : g_h1;
    #pragma unroll
    for (int c = 0; c < 8; c++) {
        int co = cb + cog * 8 + c;
        float* dst = &dst_base[(((size_t)b * COUT_C + co) * 256 + gy) * 256 + gx0 + xs];
        *(float4*)(dst)     = make_float4(acc[c][0], acc[c][1], acc[c][2], acc[c][3]);
        *(float4*)(dst + 4) = make_float4(acc[c][4], acc[c][5], acc[c][6], acc[c][7]);
    }
    if (FUSE) {
        // transposed [b][y][x][co] for coalesced point sampling
        #pragma unroll
        for (int px = 0; px < 8; px++) {
            size_t base = (((size_t)b * 256 + gy) * 256 + gx0 + xs + px) * 128 + cb + cog * 8;
            *(float4*)&g_xat[base]     = make_float4(acc[0][px], acc[1][px], acc[2][px], acc[3][px]);
            *(float4*)&g_xat[base + 4] = make_float4(acc[4][px], acc[5][px], acc[6][px], acc[7][px]);
        }
    }
}

// ---------------- bilinear sampling: one warp per point ----------------
__global__ void sample_kernel(const float* __restrict__ p)
{
    int gid  = blockIdx.x * blockDim.x + threadIdx.x;
    int wid  = gid >> 5;
    int lane = gid & 31;
    if (wid >= NPTS) return;
    int b = (wid >= N_) ? 1 : 0;

    float sx = p[(size_t)wid * 3 + 0];
    float sy = p[(size_t)wid * 3 + 1];
    float px = fminf(fmaxf(sx * 255.f, 0.f), 255.f);
    float py = fminf(fmaxf(sy * 255.f, 0.f), 255.f);
    float x0f = floorf(px), y0f = floorf(py);
    int x0 = (int)x0f, y0 = (int)y0f;
    int x1 = min(x0 + 1, 255), y1 = min(y0 + 1, 255);
    float wx = px - x0f, wy = py - y0f;
    float w00 = (1.f - wx) * (1.f - wy);
    float w01 = wx * (1.f - wy);
    float w10 = (1.f - wx) * wy;
    float w11 = wx * wy;

    const float4* F = (const float4*)g_xat;
    size_t r00 = ((size_t)(b * 256 + y0) * 256 + x0) * 32 + lane;
    size_t r01 = ((size_t)(b * 256 + y0) * 256 + x1) * 32 + lane;
    size_t r10 = ((size_t)(b * 256 + y1) * 256 + x0) * 32 + lane;
    size_t r11 = ((size_t)(b * 256 + y1) * 256 + x1) * 32 + lane;
    float4 f00 = F[r00], f01 = F[r01], f10 = F[r10], f11 = F[r11];
    float4 r;
    r.x = f00.x * w00 + f01.x * w01 + f10.x * w10 + f11.x * w11;
    r.y = f00.y * w00 + f01.y * w01 + f10.y * w10 + f11.y * w11;
    r.z = f00.z * w00 + f01.z * w01 + f10.z * w10 + f11.z * w11;
    r.w = f00.w * w00 + f01.w * w01 + f10.w * w10 + f11.w * w11;
    ((float4*)g_c0)[(size_t)wid * 32 + lane] = r;

    if (lane == 0) {
        int ix = min(max((int)(sx * 256.f), 0), 255);
        int iy = min(max((int)(sy * 256.f), 0), 255);
        int idx = ix + (iy << 8);
        g_idx[wid] = idx;
        atomicAdd(&g_cnt[b * RES2 + idx], 1.f);
    }
}

// ---------------- fc1: t = relu(c0 @ W1 + b1), M=200000, K=128, N=256 ----------------
__global__ __launch_bounds__(256)
void fc1_kernel(const float* __restrict__ W, const float* __restrict__ bias)
{
    __shared__ float As[16 * 68];
    __shared__ float Bs[16 * 64];
    const int tid = threadIdx.x;
    const int ty = tid >> 4, tx = tid & 15;
    const int m0 = blockIdx.x * 64;
    const int n0 = blockIdx.y * 64;
    float acc[4][4] = {};

    for (int k0 = 0; k0 < 128; k0 += 16) {
        __syncthreads();
        {
            int e = tid * 4;
            int am = e >> 4, ak = e & 15;
            float4 v = *(const float4*)&g_c0[(size_t)(m0 + am) * 128 + k0 + ak];
            As[(ak + 0) * 68 + am] = v.x; As[(ak + 1) * 68 + am] = v.y;
            As[(ak + 2) * 68 + am] = v.z; As[(ak + 3) * 68 + am] = v.w;
            int bk = e >> 6, bn = e & 63;
            *(float4*)&Bs[bk * 64 + bn] =
                *(const float4*)&W[(size_t)(k0 + bk) * 256 + n0 + bn];
        }
        __syncthreads();
        #pragma unroll
        for (int k = 0; k < 16; k++) {
            float4 a  = *(float4*)&As[k * 68 + ty * 4];
            float4 bq = *(float4*)&Bs[k * 64 + tx * 4];
            acc[0][0] = fmaf(a.x, bq.x, acc[0][0]); acc[0][1] = fmaf(a.x, bq.y, acc[0][1]);
            acc[0][2] = fmaf(a.x, bq.z, acc[0][2]); acc[0][3] = fmaf(a.x, bq.w, acc[0][3]);
            acc[1][0] = fmaf(a.y, bq.x, acc[1][0]); acc[1][1] = fmaf(a.y, bq.y, acc[1][1]);
            acc[1][2] = fmaf(a.y, bq.z, acc[1][2]); acc[1][3] = fmaf(a.y, bq.w, acc[1][3]);
            acc[2][0] = fmaf(a.z, bq.x, acc[2][0]); acc[2][1] = fmaf(a.z, bq.y, acc[2][1]);
            acc[2][2] = fmaf(a.z, bq.z, acc[2][2]); acc[2][3] = fmaf(a.z, bq.w, acc[2][3]);
            acc[3][0] = fmaf(a.w, bq.x, acc[3][0]); acc[3][1] = fmaf(a.w, bq.y, acc[3][1]);
            acc[3][2] = fmaf(a.w, bq.z, acc[3][2]); acc[3][3] = fmaf(a.w, bq.w, acc[3][3]);
        }
    }
    float4 bi = *(const float4*)&bias[n0 + tx * 4];
    #pragma unroll
    for (int i = 0; i < 4; i++) {
        int row = m0 + ty * 4 + i;
        float4 o = make_float4(fmaxf(acc[i][0] + bi.x, 0.f), fmaxf(acc[i][1] + bi.y, 0.f),
                               fmaxf(acc[i][2] + bi.z, 0.f), fmaxf(acc[i][3] + bi.w, 0.f));
        *(float4*)&g_t[(size_t)row * 256 + n0 + tx * 4] = o;
    }
}

// ---------------- fc2: c = t@W2 + b2 + c_last@Wc + bc; write c; scatter-add ----------------
__global__ __launch_bounds__(256)
void fc2_kernel(const float* __restrict__ W2, const float* __restrict__ b2,
                const float* __restrict__ clast, const float* __restrict__ Wc,
                const float* __restrict__ bc, float* __restrict__ outc)
{
    __shared__ float As[16 * 68];
    __shared__ float Bs[16 * 64];
    const int tid = threadIdx.x;
    const int ty = tid >> 4, tx = tid & 15;
    const int m0 = blockIdx.x * 64;
    const int n0 = blockIdx.y * 64;
    float acc[4][4] = {};

    // pass 1: K = 256 over g_t / W2 (ldb = 128)
    for (int k0 = 0; k0 < 256; k0 += 16) {
        __syncthreads();
        {
            int e = tid * 4;
            int am = e >> 4, ak = e & 15;
            float4 v = *(const float4*)&g_t[(size_t)(m0 + am) * 256 + k0 + ak];
            As[(ak + 0) * 68 + am] = v.x; As[(ak + 1) * 68 + am] = v.y;
            As[(ak + 2) * 68 + am] = v.z; As[(ak + 3) * 68 + am] = v.w;
            int bk = e >> 6, bn = e & 63;
            *(float4*)&Bs[bk * 64 + bn] =
                *(const float4*)&W2[(size_t)(k0 + bk) * 128 + n0 + bn];
        }
        __syncthreads();
        #pragma unroll
        for (int k = 0; k < 16; k++) {
            float4 a  = *(float4*)&As[k * 68 + ty * 4];
            float4 bq = *(float4*)&Bs[k * 64 + tx * 4];
            acc[0][0] = fmaf(a.x, bq.x, acc[0][0]); acc[0][1] = fmaf(a.x, bq.y, acc[0][1]);
            acc[0][2] = fmaf(a.x, bq.z, acc[0][2]); acc[0][3] = fmaf(a.x, bq.w, acc[0][3]);
            acc[1][0] = fmaf(a.y, bq.x, acc[1][0]); acc[1][1] = fmaf(a.y, bq.y, acc[1][1]);
            acc[1][2] = fmaf(a.y, bq.z, acc[1][2]); acc[1][3] = fmaf(a.y, bq.w, acc[1][3]);
            acc[2][0] = fmaf(a.z, bq.x, acc[2][0]); acc[2][1] = fmaf(a.z, bq.y, acc[2][1]);
            acc[2][2] = fmaf(a.z, bq.z, acc[2][2]); acc[2][3] = fmaf(a.z, bq.w, acc[2][3]);
            acc[3][0] = fmaf(a.w, bq.x, acc[3][0]); acc[3][1] = fmaf(a.w, bq.y, acc[3][1]);
            acc[3][2] = fmaf(a.w, bq.z, acc[3][2]); acc[3][3] = fmaf(a.w, bq.w, acc[3][3]);
        }
    }
    // pass 2: K = 64 over c_last / Wc (lda = 64, ldb = 128)
    for (int k0 = 0; k0 < 64; k0 += 16) {
        __syncthreads();
        {
            int e = tid * 4;
            int am = e >> 4, ak = e & 15;
            float4 v = *(const float4*)&clast[(size_t)(m0 + am) * 64 + k0 + ak];
            As[(ak + 0) * 68 + am] = v.x; As[(ak + 1) * 68 + am] = v.y;
            As[(ak + 2) * 68 + am] = v.z; As[(ak + 3) * 68 + am] = v.w;
            int bk = e >> 6, bn = e & 63;
            *(float4*)&Bs[bk * 64 + bn] =
                *(const float4*)&Wc[(size_t)(k0 + bk) * 128 + n0 + bn];
        }
        __syncthreads();
        #pragma unroll
        for (int k = 0; k < 16; k++) {
            float4 a  = *(float4*)&As[k * 68 + ty * 4];
            float4 bq = *(float4*)&Bs[k * 64 + tx * 4];
            acc[0][0] = fmaf(a.x, bq.x, acc[0][0]); acc[0][1] = fmaf(a.x, bq.y, acc[0][1]);
            acc[0][2] = fmaf(a.x, bq.z, acc[0][2]); acc[0][3] = fmaf(a.x, bq.w, acc[0][3]);
            acc[1][0] = fmaf(a.y, bq.x, acc[1][0]); acc[1][1] = fmaf(a.y, bq.y, acc[1][1]);
            acc[1][2] = fmaf(a.y, bq.z, acc[1][2]); acc[1][3] = fmaf(a.y, bq.w, acc[1][3]);
            acc[2][0] = fmaf(a.z, bq.x, acc[2][0]); acc[2][1] = fmaf(a.z, bq.y, acc[2][1]);
            acc[2][2] = fmaf(a.z, bq.z, acc[2][2]); acc[2][3] = fmaf(a.z, bq.w, acc[2][3]);
            acc[3][0] = fmaf(a.w, bq.x, acc[3][0]); acc[3][1] = fmaf(a.w, bq.y, acc[3][1]);
            acc[3][2] = fmaf(a.w, bq.z, acc[3][2]); acc[3][3] = fmaf(a.w, bq.w, acc[3][3]);
        }
    }

    const int col = n0 + tx * 4;
    float4 bi;
    bi.x = b2[col + 0] + bc[col + 0];
    bi.y = b2[col + 1] + bc[col + 1];
    bi.z = b2[col + 2] + bc[col + 2];
    bi.w = b2[col + 3] + bc[col + 3];
    #pragma unroll
    for (int i = 0; i < 4; i++) {
        int row = m0 + ty * 4 + i;
        float4 v = make_float4(acc[i][0] + bi.x, acc[i][1] + bi.y,
                               acc[i][2] + bi.z, acc[i][3] + bi.w);
        *(float4*)&outc[(size_t)row * 128 + col] = v;
        int idx = g_idx[row];
        int bb  = (row >= N_) ? 1 : 0;
        float* s = &g_sums[((size_t)(bb * 128 + col)) * RES2 + idx];
        atomicAdd(s + 0 * RES2, v.x);
        atomicAdd(s + 1 * RES2, v.y);
        atomicAdd(s + 2 * RES2, v.z);
        atomicAdd(s + 3 * RES2, v.w);
    }
}

// ---------------- plane finalize: before_pool = sums / max(cnt,1) ----------------
__global__ void plane_kernel(float* __restrict__ dout)
{
    int i = blockIdx.x * blockDim.x + threadIdx.x;
    if (i >= B_ * 128 * RES2) return;
    int b = i >> 23;          // 128*65536 = 2^23
    int idx = i & 65535;
    float cnt = g_cnt[(b << 16) + idx];
    dout[BP_OFF + i] = g_sums[i] / fmaxf(cnt, 1.f);
}

// ---------------- 2x2 maxpool ----------------
__global__ void pool_kernel(float* __restrict__ dout)
{
    int i = blockIdx.x * blockDim.x + threadIdx.x;
    if (i >= B_ * 128 * 128 * 128) return;
    int px = i & 127, py = (i >> 7) & 127, bc = i >> 14;
    const float* pl = dout + BP_OFF + (size_t)bc * RES2;
    int r0 = (py * 2) * 256 + px * 2;
    float v = fmaxf(fmaxf(pl[r0], pl[r0 + 1]), fmaxf(pl[r0 + 256], pl[r0 + 257]));
    dout[OUT_OFF + i] = v;
}

// ---------------- launch ----------------
extern "C" void kernel_launch(void* const* d_in, const int* in_sizes, int n_in,
                              void* d_out, int out_size)
{
    const float* p     = (const float*)d_in[0];
    const float* x_xy  = (const float*)d_in[1];
    const float* x_ac  = (const float*)d_in[2];
    const float* clast = (const float*)d_in[3];
    const float* w1    = (const float*)d_in[4];
    const float* bb1   = (const float*)d_in[5];
    const float* w2    = (const float*)d_in[6];
    const float* bb2   = (const float*)d_in[7];
    const float* w1x1  = (const float*)d_in[8];
    const float* b1x1  = (const float*)d_in[9];
    const float* wfc1  = (const float*)d_in[10];
    const float* bfc1  = (const float*)d_in[11];
    const float* wfc2  = (const float*)d_in[12];
    const float* bfc2  = (const float*)d_in[13];
    const float* wfcc  = (const float*)d_in[14];
    const float* bfcc  = (const float*)d_in[15];
    float* out = (float*)d_out;

    const size_t conv_smem = (2800 + 4608) * sizeof(float);   // 29632 B
    dim3 cgrid(8, 32, 4);  // 256/32 x-tiles, 256/8 y-tiles, B * co-blocks

    zero_kernel<<<2048, 256>>>();
    conv3x3_kernel<64, false><<<cgrid, 256, conv_smem>>>(
        x_xy, w1, bb1, nullptr, nullptr, nullptr, nullptr);
    conv3x3_kernel<128, true><<<cgrid, 256, conv_smem>>>(
        nullptr, w2, bb2, x_ac, w1x1, b1x1, out + XA_OFF);
    sample_kernel<<<(NPTS * 32 + 255) / 256, 256>>>(p);
    fc1_kernel<<<dim3(NPTS / 64, 4), 256>>>(wfc1, bfc1);
    fc2_kernel<<<dim3(NPTS / 64, 2), 256>>>(wfc2, bfc2, clast, wfcc, bfcc, out + C_OFF);
    plane_kernel<<<(B_ * 128 * RES2) / 256, 256>>>(out);
    pool_kernel<<<(B_ * 128 * 128 * 128) / 256, 256>>>(out);
}

// round 6
// speedup vs baseline: 1.0312x; 1.0312x over previous
#include <cuda_runtime.h>
#include <cuda_bf16.h>
#include <cstdint>

// Problem constants
#define B_      2
#define N_      100000
#define NPTS    (B_ * N_)          // 200000
#define RES     256
#define RES2    65536
#define CIN_C   64
#define COUT_C  128

// Output layout (concatenated, return order: out, before_pool, x_after, c)
#define OUT_OFF 0
#define BP_OFF  4194304            // 2*128*128*128
#define XA_OFF  20971520           // BP_OFF + 2*128*256*256
#define C_OFF   37748736           // XA_OFF + 2*128*256*256

#define MTILES  1563               // ceil(200000/128)

// ---------------- device scratch (no allocations allowed) ----------------
__device__ __align__(128) float g_h1[(size_t)B_ * COUT_C * RES * RES];   // conv1 output
__device__ __align__(128) float g_xat[(size_t)B_ * RES * RES * COUT_C];  // x_after transposed
__device__ __align__(128) float g_sums[(size_t)B_ * 128 * RES2];         // scatter sums
__device__ __align__(128) float g_cnt[(size_t)B_ * RES2];                // scatter counts
__device__ __align__(128) int   g_idx[NPTS];                             // per-point bin

// bf16 hi/lo split buffers for tensor-core GEMMs
__device__ __align__(128) __nv_bfloat16 g_c0h[(size_t)NPTS * 128];
__device__ __align__(128) __nv_bfloat16 g_c0l[(size_t)NPTS * 128];
__device__ __align__(128) __nv_bfloat16 g_th [(size_t)NPTS * 256];
__device__ __align__(128) __nv_bfloat16 g_tl [(size_t)NPTS * 256];
__device__ __align__(128) __nv_bfloat16 g_clh[(size_t)NPTS * 64];
__device__ __align__(128) __nv_bfloat16 g_cll[(size_t)NPTS * 64];
__device__ __align__(128) __nv_bfloat16 g_w1t_h[256 * 128];  // [N=256][K=128]
__device__ __align__(128) __nv_bfloat16 g_w1t_l[256 * 128];
__device__ __align__(128) __nv_bfloat16 g_w2t_h[128 * 256];  // [N=128][K=256]
__device__ __align__(128) __nv_bfloat16 g_w2t_l[128 * 256];
__device__ __align__(128) __nv_bfloat16 g_wct_h[128 * 64];   // [N=128][K=64]
__device__ __align__(128) __nv_bfloat16 g_wct_l[128 * 64];

// ---------------- helpers ----------------
__device__ __forceinline__ uint32_t smem_u32(const void* p) {
    uint32_t a;
    asm("{ .reg .u64 t; cvta.to.shared.u64 t, %1; cvt.u32.u64 %0, t; }" : "=r"(a) : "l"(p));
    return a;
}
#define SW128(o) ((o) ^ (((o) >> 3) & 0x70))

__device__ __forceinline__ void ldm_x4(uint32_t* r, uint32_t addr) {
    asm volatile("ldmatrix.sync.aligned.m8n8.x4.shared.b16 {%0,%1,%2,%3}, [%4];"
        : "=r"(r[0]), "=r"(r[1]), "=r"(r[2]), "=r"(r[3]) : "r"(addr));
}
__device__ __forceinline__ void mma16816(float* c, const uint32_t* a, const uint32_t* b) {
    asm volatile("mma.sync.aligned.m16n8k16.row.col.f32.bf16.bf16.f32 "
        "{%0,%1,%2,%3}, {%4,%5,%6,%7}, {%8,%9}, {%0,%1,%2,%3};"
        : "+f"(c[0]), "+f"(c[1]), "+f"(c[2]), "+f"(c[3])
        : "r"(a[0]), "r"(a[1]), "r"(a[2]), "r"(a[3]), "r"(b[0]), "r"(b[1]));
}

// bf16 hi/lo split of two floats, packed as bf16x2 words
__device__ __forceinline__ void split2(float a, float b, uint32_t& uh, uint32_t& ul) {
    __nv_bfloat16 ha = __float2bfloat16(a), hb = __float2bfloat16(b);
    float ra = a - __bfloat162float(ha), rb = b - __bfloat162float(hb);
    __nv_bfloat16 la = __float2bfloat16(ra), lb = __float2bfloat16(rb);
    uh = ((uint32_t)__bfloat16_as_ushort(hb) << 16) | __bfloat16_as_ushort(ha);
    ul = ((uint32_t)__bfloat16_as_ushort(lb) << 16) | __bfloat16_as_ushort(la);
}

// ---------------- zero scratch accumulators ----------------
__global__ void zero_kernel() {
    const size_t ns = (size_t)B_ * 128 * RES2;
    const size_t total = ns + (size_t)B_ * RES2;
    for (size_t i = (size_t)blockIdx.x * blockDim.x + threadIdx.x; i < total;
         i += (size_t)gridDim.x * blockDim.x) {
        if (i < ns) g_sums[i] = 0.f;
        else        g_cnt[i - ns] = 0.f;
    }
}

// ---------------- direct 3x3 conv, register-tiled (unchanged from R1) ----------------
template<int CIN, bool FUSE>
__global__ __launch_bounds__(256, 2)
void conv3x3_kernel(const float* __restrict__ in_param,
                    const float* __restrict__ w,
                    const float* __restrict__ bias,
                    const float* __restrict__ x1,
                    const float* __restrict__ w1,
                    const float* __restrict__ b1,
                    float* __restrict__ out_std)
{
    extern __shared__ float smf[];
    float* s_in = smf;
    float* s_w  = smf + 2800;

    const int tid = threadIdx.x;
    const int cog = tid >> 5;
    const int pix = tid & 31;
    const int xs  = (pix & 3) * 8;
    const int ty  = pix >> 2;

    const int bx = blockIdx.x, by = blockIdx.y;
    const int b  = blockIdx.z >> 1;
    const int cb = (blockIdx.z & 1) * 64;

    const float* src = FUSE ? g_h1 : in_param;

    float acc[8][8];
    #pragma unroll
    for (int c = 0; c < 8; c++)
        #pragma unroll
        for (int px = 0; px < 8; px++) acc[c][px] = 0.f;

    const int gy0 = by * 8, gx0 = bx * 32;

    for (int ch = 0; ch < CIN / 8; ch++) {
        __syncthreads();
        for (int e = tid; e < 8 * 10 * 34; e += 256) {
            int ci = e / 340; int r = e - ci * 340;
            int yy = r / 34;  int xx = r - yy * 34;
            int gy = gy0 - 1 + yy, gx = gx0 - 1 + xx;
            float v = 0.f;
            if ((unsigned)gy < 256u && (unsigned)gx < 256u)
                v = src[(((size_t)b * CIN + ch * 8 + ci) * 256 + gy) * 256 + gx];
            s_in[ci * 350 + yy * 35 + xx] = v;
        }
        for (int e = tid; e < 64 * 8 * 9; e += 256) {
            int co = e / 72; int r = e - co * 72;
            s_w[e] = w[((size_t)(cb + co) * CIN + ch * 8) * 9 + r];
        }
        __syncthreads();

        #pragma unroll 1
        for (int ci = 0; ci < 8; ci++) {
            #pragma unroll
            for (int ky = 0; ky < 3; ky++) {
                float inrow[10];
                #pragma unroll
                for (int j = 0; j < 10; j++)
                    inrow[j] = s_in[ci * 350 + (ty + ky) * 35 + xs + j];
                #pragma unroll
                for (int kx = 0; kx < 3; kx++) {
                    #pragma unroll
                    for (int c = 0; c < 8; c++) {
                        float wv = s_w[(cog * 8 + c) * 72 + ci * 9 + ky * 3 + kx];
                        #pragma unroll
                        for (int px = 0; px < 8; px++)
                            acc[c][px] = fmaf(inrow[px + kx], wv, acc[c][px]);
                    }
                }
            }
        }
    }

    #pragma unroll
    for (int c = 0; c < 8; c++) {
        float bv = bias[cb + cog * 8 + c];
        #pragma unroll
        for (int px = 0; px < 8; px++)
            acc[c][px] = fmaxf(acc[c][px] + bv, 0.f);
    }

    if (FUSE) {
        float* s_in1 = smf;
        float* s_w1  = smf + 2112;
        #pragma unroll
        for (int c = 0; c < 8; c++) {
            float bv = b1[cb + cog * 8 + c];
            #pragma unroll
            for (int px = 0; px < 8; px++) acc[c][px] += bv;
        }
        for (int ch = 0; ch < 64 / 8; ch++) {
            __syncthreads();
            for (int e = tid; e < 8 * 8 * 32; e += 256) {
                int ci = e >> 8; int yy = (e >> 5) & 7; int xx = e & 31;
                s_in1[ci * 264 + yy * 33 + xx] =
                    x1[(((size_t)b * 64 + ch * 8 + ci) * 256 + gy0 + yy) * 256 + gx0 + xx];
            }
            for (int e = tid; e < 512; e += 256)
                s_w1[e] = w1[(size_t)(cb + (e >> 3)) * 64 + ch * 8 + (e & 7)];
            __syncthreads();
            #pragma unroll 1
            for (int ci = 0; ci < 8; ci++) {
                float inv[8];
                #pragma unroll
                for (int j = 0; j < 8; j++)
                    inv[j] = s_in1[ci * 264 + ty * 33 + xs + j];
                #pragma unroll
                for (int c = 0; c < 8; c++) {
                    float wv = s_w1[(cog * 8 + c) * 8 + ci];
                    #pragma unroll
                    for (int px = 0; px < 8; px++)
                        acc[c][px] = fmaf(inv[px], wv, acc[c][px]);
                }
            }
        }
    }

    const int gy = gy0 + ty;
    float* dst_base = FUSE ? out_std : g_h1;
    #pragma unroll
    for (int c = 0; c < 8; c++) {
        int co = cb + cog * 8 + c;
        float* dst = &dst_base[(((size_t)b * COUT_C + co) * 256 + gy) * 256 + gx0 + xs];
        *(float4*)(dst)     = make_float4(acc[c][0], acc[c][1], acc[c][2], acc[c][3]);
        *(float4*)(dst + 4) = make_float4(acc[c][4], acc[c][5], acc[c][6], acc[c][7]);
    }
    if (FUSE) {
        #pragma unroll
        for (int px = 0; px < 8; px++) {
            size_t base = (((size_t)b * 256 + gy) * 256 + gx0 + xs + px) * 128 + cb + cog * 8;
            *(float4*)&g_xat[base]     = make_float4(acc[0][px], acc[1][px], acc[2][px], acc[3][px]);
            *(float4*)&g_xat[base + 4] = make_float4(acc[4][px], acc[5][px], acc[6][px], acc[7][px]);
        }
    }
}

// ---------------- bilinear sampling: one warp per point; writes bf16 hi/lo ----------------
__global__ void sample_kernel(const float* __restrict__ p)
{
    int gid  = blockIdx.x * blockDim.x + threadIdx.x;
    int wid  = gid >> 5;
    int lane = gid & 31;
    if (wid >= NPTS) return;
    int b = (wid >= N_) ? 1 : 0;

    float sx = p[(size_t)wid * 3 + 0];
    float sy = p[(size_t)wid * 3 + 1];
    float px = fminf(fmaxf(sx * 255.f, 0.f), 255.f);
    float py = fminf(fmaxf(sy * 255.f, 0.f), 255.f);
    float x0f = floorf(px), y0f = floorf(py);
    int x0 = (int)x0f, y0 = (int)y0f;
    int x1 = min(x0 + 1, 255), y1 = min(y0 + 1, 255);
    float wx = px - x0f, wy = py - y0f;
    float w00 = (1.f - wx) * (1.f - wy);
    float w01 = wx * (1.f - wy);
    float w10 = (1.f - wx) * wy;
    float w11 = wx * wy;

    const float4* F = (const float4*)g_xat;
    size_t r00 = ((size_t)(b * 256 + y0) * 256 + x0) * 32 + lane;
    size_t r01 = ((size_t)(b * 256 + y0) * 256 + x1) * 32 + lane;
    size_t r10 = ((size_t)(b * 256 + y1) * 256 + x0) * 32 + lane;
    size_t r11 = ((size_t)(b * 256 + y1) * 256 + x1) * 32 + lane;
    float4 f00 = F[r00], f01 = F[r01], f10 = F[r10], f11 = F[r11];
    float4 r;
    r.x = f00.x * w00 + f01.x * w01 + f10.x * w10 + f11.x * w11;
    r.y = f00.y * w00 + f01.y * w01 + f10.y * w10 + f11.y * w11;
    r.z = f00.z * w00 + f01.z * w01 + f10.z * w10 + f11.z * w11;
    r.w = f00.w * w00 + f01.w * w01 + f10.w * w10 + f11.w * w11;

    uint32_t h0, l0, h1, l1;
    split2(r.x, r.y, h0, l0);
    split2(r.z, r.w, h1, l1);
    uint32_t* ch = (uint32_t*)g_c0h;
    uint32_t* cl = (uint32_t*)g_c0l;
    size_t base = (size_t)wid * 64 + lane * 2;
    ch[base] = h0; ch[base + 1] = h1;
    cl[base] = l0; cl[base + 1] = l1;

    if (lane == 0) {
        int ix = min(max((int)(sx * 256.f), 0), 255);
        int iy = min(max((int)(sy * 256.f), 0), 255);
        int idx = ix + (iy << 8);
        g_idx[wid] = idx;
        atomicAdd(&g_cnt[b * RES2 + idx], 1.f);
    }
}

// ---------------- c_last -> bf16 hi/lo ----------------
__global__ void clconv_kernel(const float* __restrict__ clast)
{
    int i = blockIdx.x * blockDim.x + threadIdx.x;
    if (i >= NPTS * 32) return;   // pairs
    float a = clast[2 * i], b = clast[2 * i + 1];
    uint32_t uh, ul;
    split2(a, b, uh, ul);
    ((uint32_t*)g_clh)[i] = uh;
    ((uint32_t*)g_cll)[i] = ul;
}

// ---------------- weight transpose + bf16 hi/lo split ----------------
__global__ void wconv_kernel(const float* __restrict__ W1,
                             const float* __restrict__ W2,
                             const float* __restrict__ Wc)
{
    int i = blockIdx.x * blockDim.x + threadIdx.x;
    if (i < 256 * 128) {
        int n = i >> 7, k = i & 127;
        float v = W1[k * 256 + n];
        __nv_bfloat16 h = __float2bfloat16(v);
        g_w1t_h[i] = h;
        g_w1t_l[i] = __float2bfloat16(v - __bfloat162float(h));
    }
    if (i < 128 * 256) {
        int n = i >> 8, k = i & 255;
        float v = W2[k * 128 + n];
        __nv_bfloat16 h = __float2bfloat16(v);
        g_w2t_h[i] = h;
        g_w2t_l[i] = __float2bfloat16(v - __bfloat162float(h));
    }
    if (i < 128 * 64) {
        int n = i >> 6, k = i & 63;
        float v = Wc[k * 128 + n];
        __nv_bfloat16 h = __float2bfloat16(v);
        g_wct_h[i] = h;
        g_wct_l[i] = __float2bfloat16(v - __bfloat162float(h));
    }
}

// ---------------- HMMA GEMM core (mma.sync m16n8k16 bf16) ----------------
// Block: 256 thr = 8 warps (4 M x 2 N). Block tile 128x128, warp tile 32x64.
// K staged 64-wide in SW128-swizzled smem; ldmatrix.x4 for A and B fragments.
// A: row-major [M][lda]; B: N-major [N][ldb] (exactly .col operand layout).
__device__ __forceinline__ void gemm_chunk(
    char* smAp, char* smBp, uint32_t smAb, uint32_t smBb,
    const __nv_bfloat16* __restrict__ Ag, int lda, int m0,
    const __nv_bfloat16* __restrict__ Bg, int ldb, int n0, int koff,
    int tid, int warp_m, int warp_n, int lane,
    float acc[2][8][4])
{
    __syncthreads();
    // stage A tile [128][64]
    for (int e = tid; e < 1024; e += 256) {
        int row = e >> 3, uc = e & 7;
        int grow = m0 + row;
        uint4 v = make_uint4(0, 0, 0, 0);
        if (grow < NPTS)
            v = *(const uint4*)(Ag + (size_t)grow * lda + koff + uc * 8);
        *(uint4*)(smAp + SW128(row * 128 + uc * 16)) = v;
    }
    // stage B tile [128][64]
    for (int e = tid; e < 1024; e += 256) {
        int row = e >> 3, uc = e & 7;
        uint4 v = *(const uint4*)(Bg + (size_t)(n0 + row) * ldb + koff + uc * 8);
        *(uint4*)(smBp + SW128(row * 128 + uc * 16)) = v;
    }
    __syncthreads();

    #pragma unroll
    for (int ks = 0; ks < 4; ks++) {
        int kc = ks * 2;
        uint32_t a[2][4];
        #pragma unroll
        for (int i = 0; i < 2; i++) {
            int r = warp_m * 32 + i * 16 + (lane & 15);
            int c = kc + (lane >> 4);
            ldm_x4(a[i], smAb + SW128((uint32_t)(r * 128 + c * 16)));
        }
        uint32_t b[8][2];
        #pragma unroll
        for (int j2 = 0; j2 < 4; j2++) {
            int r = warp_n * 64 + j2 * 16 + (lane & 15);
            int c = kc + (lane >> 4);
            uint32_t t[4];
            ldm_x4(t, smBb + SW128((uint32_t)(r * 128 + c * 16)));
            b[j2 * 2][0] = t[0]; b[j2 * 2 + 1][0] = t[1];
            b[j2 * 2][1] = t[2]; b[j2 * 2 + 1][1] = t[3];
        }
        #pragma unroll
        for (int i = 0; i < 2; i++)
            #pragma unroll
            for (int j = 0; j < 8; j++)
                mma16816(acc[i][j], a[i], b[j]);
    }
}

// ---------------- fc1: t = relu(c0 @ W1 + b1), 3-term bf16 split ----------------
__global__ __launch_bounds__(256)
void fc1_hmma_kernel(const float* __restrict__ bias)
{
    __shared__ __align__(128) __nv_bfloat16 smA[128 * 64];
    __shared__ __align__(128) __nv_bfloat16 smB[128 * 64];
    char* smAp = (char*)smA; char* smBp = (char*)smB;
    uint32_t smAb = smem_u32(smA), smBb = smem_u32(smB);

    const int tid = threadIdx.x, lane = tid & 31, wid = tid >> 5;
    const int warp_m = wid & 3, warp_n = wid >> 2;
    const int m0 = blockIdx.x * 128, n0 = blockIdx.y * 128;

    float acc[2][8][4] = {};

    const __nv_bfloat16* Aph[3] = {g_c0h, g_c0l, g_c0h};
    const __nv_bfloat16* Bph[3] = {g_w1t_h, g_w1t_h, g_w1t_l};
    for (int ph = 0; ph < 3; ph++)
        for (int kc = 0; kc < 2; kc++)
            gemm_chunk(smAp, smBp, smAb, smBb, Aph[ph], 128, m0,
                       Bph[ph], 128, n0, kc * 64, tid, warp_m, warp_n, lane, acc);

    // epilogue: bias + relu -> split hi/lo -> g_th/g_tl [M][256] (as u32 [M][128])
    uint32_t* th = (uint32_t*)g_th;
    uint32_t* tl = (uint32_t*)g_tl;
    const int g = lane >> 2, t4 = lane & 3;
    #pragma unroll
    for (int i = 0; i < 2; i++) {
        int rowA = m0 + warp_m * 32 + i * 16 + g;
        int rowB = rowA + 8;
        #pragma unroll
        for (int j = 0; j < 8; j++) {
            int col = n0 + warp_n * 64 + j * 8 + t4 * 2;
            float b0 = bias[col], b1 = bias[col + 1];
            if (rowA < NPTS) {
                float v0 = fmaxf(acc[i][j][0] + b0, 0.f);
                float v1 = fmaxf(acc[i][j][1] + b1, 0.f);
                uint32_t uh, ul; split2(v0, v1, uh, ul);
                size_t o = (size_t)rowA * 128 + (col >> 1);
                th[o] = uh; tl[o] = ul;
            }
            if (rowB < NPTS) {
                float v2 = fmaxf(acc[i][j][2] + b0, 0.f);
                float v3 = fmaxf(acc[i][j][3] + b1, 0.f);
                uint32_t uh, ul; split2(v2, v3, uh, ul);
                size_t o = (size_t)rowB * 128 + (col >> 1);
                th[o] = uh; tl[o] = ul;
            }
        }
    }
}

// ---------------- fc2: c = t@W2 + b2 + c_last@Wc + bc; write c; scatter-add ----------------
__global__ __launch_bounds__(256)
void fc2_hmma_kernel(const float* __restrict__ b2, const float* __restrict__ bc,
                     float* __restrict__ outc)
{
    __shared__ __align__(128) __nv_bfloat16 smA[128 * 64];
    __shared__ __align__(128) __nv_bfloat16 smB[128 * 64];
    char* smAp = (char*)smA; char* smBp = (char*)smB;
    uint32_t smAb = smem_u32(smA), smBb = smem_u32(smB);

    const int tid = threadIdx.x, lane = tid & 31, wid = tid >> 5;
    const int warp_m = wid & 3, warp_n = wid >> 2;
    const int m0 = blockIdx.x * 128;

    float acc[2][8][4] = {};

    // phases over t (K=256) then c_last (K=64), each 3-term
    const __nv_bfloat16* Aph[6] = {g_th, g_tl, g_th, g_clh, g_cll, g_clh};
    const __nv_bfloat16* Bph[6] = {g_w2t_h, g_w2t_h, g_w2t_l, g_wct_h, g_wct_h, g_wct_l};
    const int ldp[6] = {256, 256, 256, 64, 64, 64};
    const int ncp[6] = {4, 4, 4, 1, 1, 1};
    for (int ph = 0; ph < 6; ph++)
        for (int kc = 0; kc < ncp[ph]; kc++)
            gemm_chunk(smAp, smBp, smAb, smBb, Aph[ph], ldp[ph], m0,
                       Bph[ph], ldp[ph], 0, kc * 64, tid, warp_m, warp_n, lane, acc);

    // epilogue: +biases, write c, fused scatter-add
    const int g = lane >> 2, t4 = lane & 3;
    int rows[4], idxs[4], bbs[4];
    #pragma unroll
    for (int i = 0; i < 2; i++) {
        rows[i * 2]     = m0 + warp_m * 32 + i * 16 + g;
        rows[i * 2 + 1] = rows[i * 2] + 8;
    }
    #pragma unroll
    for (int k = 0; k < 4; k++) {
        idxs[k] = 0; bbs[k] = 0;
        if (rows[k] < NPTS) { idxs[k] = g_idx[rows[k]]; bbs[k] = (rows[k] >= N_) ? 1 : 0; }
    }
    #pragma unroll
    for (int i = 0; i < 2; i++) {
        #pragma unroll
        for (int j = 0; j < 8; j++) {
            int col = warp_n * 64 + j * 8 + t4 * 2;
            float bb0 = b2[col] + bc[col], bb1 = b2[col + 1] + bc[col + 1];
            int rA = rows[i * 2], rB = rows[i * 2 + 1];
            float v0 = acc[i][j][0] + bb0, v1 = acc[i][j][1] + bb1;
            float v2 = acc[i][j][2] + bb0, v3 = acc[i][j][3] + bb1;
            if (rA < NPTS) {
                *(float2*)(outc + (size_t)rA * 128 + col) = make_float2(v0, v1);
                int ia = idxs[i * 2], ba = bbs[i * 2];
                atomicAdd(&g_sums[((size_t)(ba * 128 + col)) * RES2 + ia], v0);
                atomicAdd(&g_sums[((size_t)(ba * 128 + col + 1)) * RES2 + ia], v1);
            }
            if (rB < NPTS) {
                *(float2*)(outc + (size_t)rB * 128 + col) = make_float2(v2, v3);
                int ib = idxs[i * 2 + 1], bbx = bbs[i * 2 + 1];
                atomicAdd(&g_sums[((size_t)(bbx * 128 + col)) * RES2 + ib], v2);
                atomicAdd(&g_sums[((size_t)(bbx * 128 + col + 1)) * RES2 + ib], v3);
            }
        }
    }
}

// ---------------- plane finalize + maxpool ----------------
__global__ void plane_kernel(float* __restrict__ dout)
{
    int i = blockIdx.x * blockDim.x + threadIdx.x;
    if (i >= B_ * 128 * RES2) return;
    int b = i >> 23;
    int idx = i & 65535;
    float cnt = g_cnt[(b << 16) + idx];
    dout[BP_OFF + i] = g_sums[i] / fmaxf(cnt, 1.f);
}

__global__ void pool_kernel(float* __restrict__ dout)
{
    int i = blockIdx.x * blockDim.x + threadIdx.x;
    if (i >= B_ * 128 * 128 * 128) return;
    int px = i & 127, py = (i >> 7) & 127, bc = i >> 14;
    const float* pl = dout + BP_OFF + (size_t)bc * RES2;
    int r0 = (py * 2) * 256 + px * 2;
    float v = fmaxf(fmaxf(pl[r0], pl[r0 + 1]), fmaxf(pl[r0 + 256], pl[r0 + 257]));
    dout[OUT_OFF + i] = v;
}

// ---------------- launch ----------------
extern "C" void kernel_launch(void* const* d_in, const int* in_sizes, int n_in,
                              void* d_out, int out_size)
{
    const float* p     = (const float*)d_in[0];
    const float* x_xy  = (const float*)d_in[1];
    const float* x_ac  = (const float*)d_in[2];
    const float* clast = (const float*)d_in[3];
    const float* w1    = (const float*)d_in[4];
    const float* bb1   = (const float*)d_in[5];
    const float* w2    = (const float*)d_in[6];
    const float* bb2   = (const float*)d_in[7];
    const float* w1x1  = (const float*)d_in[8];
    const float* b1x1  = (const float*)d_in[9];
    const float* wfc1  = (const float*)d_in[10];
    const float* bfc1  = (const float*)d_in[11];
    const float* wfc2  = (const float*)d_in[12];
    const float* bfc2  = (const float*)d_in[13];
    const float* wfcc  = (const float*)d_in[14];
    const float* bfcc  = (const float*)d_in[15];
    float* out = (float*)d_out;

    const size_t conv_smem = (2800 + 4608) * sizeof(float);
    dim3 cgrid(8, 32, 4);

    zero_kernel<<<2048, 256>>>();
    wconv_kernel<<<128, 256>>>(wfc1, wfc2, wfcc);
    clconv_kernel<<<(NPTS * 32 + 255) / 256, 256>>>(clast);
    conv3x3_kernel<64, false><<<cgrid, 256, conv_smem>>>(
        x_xy, w1, bb1, nullptr, nullptr, nullptr, nullptr);
    conv3x3_kernel<128, true><<<cgrid, 256, conv_smem>>>(
        nullptr, w2, bb2, x_ac, w1x1, b1x1, out + XA_OFF);
    sample_kernel<<<(NPTS * 32 + 255) / 256, 256>>>(p);
    fc1_hmma_kernel<<<dim3(MTILES, 2), 256>>>(bfc1);
    fc2_hmma_kernel<<<dim3(MTILES, 1), 256>>>(bfc2, bfcc, out + C_OFF);
    plane_kernel<<<(B_ * 128 * RES2) / 256, 256>>>(out);
    pool_kernel<<<(B_ * 128 * 128 * 128) / 256, 256>>>(out);
}

// round 7
// speedup vs baseline: 1.3733x; 1.3318x over previous
#include <cuda_runtime.h>
#include <cuda_bf16.h>
#include <cstdint>

// Problem constants
#define B_      2
#define N_      100000
#define NPTS    (B_ * N_)          // 200000
#define RES     256
#define RES2    65536
#define NPIX    (B_ * RES * RES)   // 131072

// Output layout (concatenated, return order: out, before_pool, x_after, c)
#define OUT_OFF 0
#define BP_OFF  4194304            // 2*128*128*128
#define XA_OFF  20971520           // BP_OFF + 2*128*256*256
#define C_OFF   37748736           // XA_OFF + 2*128*256*256

#define MTILES  1563               // ceil(200000/128)

// ---------------- device scratch (no allocations allowed) ----------------
__device__ __align__(128) float g_xat[(size_t)NPIX * 128];     // x_after [b][y][x][c] fp32
__device__ __align__(128) float g_sums[(size_t)B_ * 128 * RES2];
__device__ __align__(128) float g_cnt[(size_t)B_ * RES2];
__device__ __align__(128) int   g_idx[NPTS];

// channel-last bf16 hi/lo activations
__device__ __align__(128) __nv_bfloat16 g_x1h[(size_t)NPIX * 64];   // x_xy
__device__ __align__(128) __nv_bfloat16 g_x1l[(size_t)NPIX * 64];
__device__ __align__(128) __nv_bfloat16 g_xah[(size_t)NPIX * 64];   // x_after_conv
__device__ __align__(128) __nv_bfloat16 g_xal[(size_t)NPIX * 64];
__device__ __align__(128) __nv_bfloat16 g_c1h[(size_t)NPIX * 128];  // relu(conv1)
__device__ __align__(128) __nv_bfloat16 g_c1l[(size_t)NPIX * 128];
__device__ __align__(128) __nv_bfloat16 g_c2h[(size_t)NPIX * 128];  // relu(conv2)
__device__ __align__(128) __nv_bfloat16 g_c2l[(size_t)NPIX * 128];

// point-pipeline bf16 hi/lo
__device__ __align__(128) __nv_bfloat16 g_c0h[(size_t)NPTS * 128];
__device__ __align__(128) __nv_bfloat16 g_c0l[(size_t)NPTS * 128];
__device__ __align__(128) __nv_bfloat16 g_th [(size_t)NPTS * 256];
__device__ __align__(128) __nv_bfloat16 g_tl [(size_t)NPTS * 256];
__device__ __align__(128) __nv_bfloat16 g_clh[(size_t)NPTS * 64];
__device__ __align__(128) __nv_bfloat16 g_cll[(size_t)NPTS * 64];

// packed weights bf16 hi/lo
__device__ __align__(128) __nv_bfloat16 g_w1t_h[256 * 128];   // fc1 [N][K]
__device__ __align__(128) __nv_bfloat16 g_w1t_l[256 * 128];
__device__ __align__(128) __nv_bfloat16 g_w2t_h[128 * 256];   // fc2 [N][K]
__device__ __align__(128) __nv_bfloat16 g_w2t_l[128 * 256];
__device__ __align__(128) __nv_bfloat16 g_wct_h[128 * 64];    // fcc [N][K]
__device__ __align__(128) __nv_bfloat16 g_wct_l[128 * 64];
__device__ __align__(128) __nv_bfloat16 g_wc1h[9 * 128 * 64];   // conv1 [tap][co][ci]
__device__ __align__(128) __nv_bfloat16 g_wc1l[9 * 128 * 64];
__device__ __align__(128) __nv_bfloat16 g_wc2h[9 * 128 * 128];  // conv2 [tap][co][ci]
__device__ __align__(128) __nv_bfloat16 g_wc2l[9 * 128 * 128];
__device__ __align__(128) __nv_bfloat16 g_wxh[128 * 64];        // conv1x1 [co][ci]
__device__ __align__(128) __nv_bfloat16 g_wxl[128 * 64];

// ---------------- helpers ----------------
__device__ __forceinline__ uint32_t smem_u32(const void* p) {
    uint32_t a;
    asm("{ .reg .u64 t; cvta.to.shared.u64 t, %1; cvt.u32.u64 %0, t; }" : "=r"(a) : "l"(p));
    return a;
}
#define SW128(o) ((o) ^ (((o) >> 3) & 0x70))

__device__ __forceinline__ void ldm_x4(uint32_t* r, uint32_t addr) {
    asm volatile("ldmatrix.sync.aligned.m8n8.x4.shared.b16 {%0,%1,%2,%3}, [%4];"
        : "=r"(r[0]), "=r"(r[1]), "=r"(r[2]), "=r"(r[3]) : "r"(addr));
}
__device__ __forceinline__ void mma16816(float* c, const uint32_t* a, const uint32_t* b) {
    asm volatile("mma.sync.aligned.m16n8k16.row.col.f32.bf16.bf16.f32 "
        "{%0,%1,%2,%3}, {%4,%5,%6,%7}, {%8,%9}, {%0,%1,%2,%3};"
        : "+f"(c[0]), "+f"(c[1]), "+f"(c[2]), "+f"(c[3])
        : "r"(a[0]), "r"(a[1]), "r"(a[2]), "r"(a[3]), "r"(b[0]), "r"(b[1]));
}

__device__ __forceinline__ void split2(float a, float b, uint32_t& uh, uint32_t& ul) {
    __nv_bfloat16 ha = __float2bfloat16(a), hb = __float2bfloat16(b);
    float ra = a - __bfloat162float(ha), rb = b - __bfloat162float(hb);
    __nv_bfloat16 la = __float2bfloat16(ra), lb = __float2bfloat16(rb);
    uh = ((uint32_t)__bfloat16_as_ushort(hb) << 16) | __bfloat16_as_ushort(ha);
    ul = ((uint32_t)__bfloat16_as_ushort(lb) << 16) | __bfloat16_as_ushort(la);
}
__device__ __forceinline__ float bf2f_lo(uint32_t u) {
    return __bfloat162float(__ushort_as_bfloat16((unsigned short)(u & 0xFFFF)));
}
__device__ __forceinline__ float bf2f_hi(uint32_t u) {
    return __bfloat162float(__ushort_as_bfloat16((unsigned short)(u >> 16)));
}

// shared warp-level compute on staged [rows][64] SW128 tiles
__device__ __forceinline__ void mma_block_pass(uint32_t smAb, uint32_t smBb, int rowoff,
                                               int warp_m, int warp_n, int lane,
                                               float acc[2][8][4])
{
    #pragma unroll
    for (int ks = 0; ks < 4; ks++) {
        int kc = ks * 2;
        uint32_t a[2][4];
        #pragma unroll
        for (int i = 0; i < 2; i++) {
            int r = warp_m * 32 + i * 16 + (lane & 15) + rowoff;
            int c = kc + (lane >> 4);
            ldm_x4(a[i], smAb + SW128((uint32_t)(r * 128 + c * 16)));
        }
        uint32_t b[8][2];
        #pragma unroll
        for (int j2 = 0; j2 < 4; j2++) {
            int r = warp_n * 64 + j2 * 16 + (lane & 15);
            int c = kc + (lane >> 4);
            uint32_t t[4];
            ldm_x4(t, smBb + SW128((uint32_t)(r * 128 + c * 16)));
            b[j2 * 2][0] = t[0]; b[j2 * 2 + 1][0] = t[1];
            b[j2 * 2][1] = t[2]; b[j2 * 2 + 1][1] = t[3];
        }
        #pragma unroll
        for (int i = 0; i < 2; i++)
            #pragma unroll
            for (int j = 0; j < 8; j++)
                mma16816(acc[i][j], a[i], b[j]);
    }
}

// ---------------- zero scratch accumulators ----------------
__global__ void zero_kernel() {
    const size_t ns = (size_t)B_ * 128 * RES2;
    const size_t total = ns + (size_t)B_ * RES2;
    for (size_t i = (size_t)blockIdx.x * blockDim.x + threadIdx.x; i < total;
         i += (size_t)gridDim.x * blockDim.x) {
        if (i < ns) g_sums[i] = 0.f;
        else        g_cnt[i - ns] = 0.f;
    }
}

// ---------------- input NCHW fp32 -> channel-last bf16 hi/lo ----------------
__global__ void cvt_kernel(const float* __restrict__ src, int sel)
{
    __shared__ float s[64 * 65];
    uint32_t* dh = sel ? (uint32_t*)g_xah : (uint32_t*)g_x1h;
    uint32_t* dl = sel ? (uint32_t*)g_xal : (uint32_t*)g_x1l;
    int tid = threadIdx.x;
    int x0 = blockIdx.x * 64, y = blockIdx.y, b = blockIdx.z;
    #pragma unroll
    for (int i = 0; i < 16; i++) {
        int lin = tid + i * 256;
        int x = lin & 63, ci = lin >> 6;
        s[x * 65 + ci] = src[(((size_t)b * 64 + ci) * 256 + y) * 256 + x0 + x];
    }
    __syncthreads();
    #pragma unroll
    for (int i = 0; i < 8; i++) {
        int lin = tid + i * 256;
        int c2 = lin & 31, x = lin >> 5;
        float a = s[x * 65 + c2 * 2], bb = s[x * 65 + c2 * 2 + 1];
        uint32_t uh, ul; split2(a, bb, uh, ul);
        size_t o = (((size_t)b * 256 + y) * 256 + x0 + x) * 32 + c2;
        dh[o] = uh; dl[o] = ul;
    }
}

// ---------------- c_last -> bf16 hi/lo ----------------
__global__ void clconv_kernel(const float* __restrict__ clast)
{
    int i = blockIdx.x * blockDim.x + threadIdx.x;
    if (i >= NPTS * 32) return;
    float a = clast[2 * i], b = clast[2 * i + 1];
    uint32_t uh, ul;
    split2(a, b, uh, ul);
    ((uint32_t*)g_clh)[i] = uh;
    ((uint32_t*)g_cll)[i] = ul;
}

// ---------------- weight packing ----------------
__global__ void wconv_kernel(const float* __restrict__ W1, const float* __restrict__ W2,
                             const float* __restrict__ Wc, const float* __restrict__ WC1,
                             const float* __restrict__ WC2, const float* __restrict__ WX)
{
    int i = blockIdx.x * blockDim.x + threadIdx.x;
    if (i < 256 * 128) {            // fc1: [K=128][N=256] -> [N][K]
        int n = i >> 7, k = i & 127;
        float v = W1[k * 256 + n];
        __nv_bfloat16 h = __float2bfloat16(v);
        g_w1t_h[i] = h; g_w1t_l[i] = __float2bfloat16(v - __bfloat162float(h));
    }
    if (i < 128 * 256) {            // fc2
        int n = i >> 8, k = i & 255;
        float v = W2[k * 128 + n];
        __nv_bfloat16 h = __float2bfloat16(v);
        g_w2t_h[i] = h; g_w2t_l[i] = __float2bfloat16(v - __bfloat162float(h));
    }
    if (i < 128 * 64) {             // fcc
        int n = i >> 6, k = i & 63;
        float v = Wc[k * 128 + n];
        __nv_bfloat16 h = __float2bfloat16(v);
        g_wct_h[i] = h; g_wct_l[i] = __float2bfloat16(v - __bfloat162float(h));
    }
    if (i < 9 * 128 * 64) {         // conv1 OIHW -> [tap][co][ci]
        int t = i / 8192; int r = i - t * 8192; int co = r >> 6, ci = r & 63;
        float v = WC1[((size_t)(co * 64 + ci)) * 9 + t];
        __nv_bfloat16 h = __float2bfloat16(v);
        g_wc1h[i] = h; g_wc1l[i] = __float2bfloat16(v - __bfloat162float(h));
    }
    if (i < 9 * 128 * 128) {        // conv2 OIHW -> [tap][co][ci]
        int t = i / 16384; int r = i & 16383; int co = r >> 7, ci = r & 127;
        float v = WC2[((size_t)(co * 128 + ci)) * 9 + t];
        __nv_bfloat16 h = __float2bfloat16(v);
        g_wc2h[i] = h; g_wc2l[i] = __float2bfloat16(v - __bfloat162float(h));
    }
    if (i < 128 * 64) {             // conv1x1 [co][ci]
        float v = WX[i];
        __nv_bfloat16 h = __float2bfloat16(v);
        g_wxh[i] = h; g_wxl[i] = __float2bfloat16(v - __bfloat162float(h));
    }
}

// ---------------- conv staging ----------------
__device__ __forceinline__ void conv_stageA(char* smAp, const __nv_bfloat16* rowsrc,
                                            int x0, int rowok, int ldci, int tid)
{
    __syncthreads();
    for (int e = tid; e < 1040; e += 256) {
        int r = e >> 3, q = e & 7;
        int gx = x0 - 1 + r;
        uint4 v = make_uint4(0, 0, 0, 0);
        if (rowok && (unsigned)gx < 256u)
            v = *(const uint4*)(rowsrc + (size_t)gx * ldci + q * 8);
        *(uint4*)(smAp + SW128(r * 128 + q * 16)) = v;
    }
    __syncthreads();
}
__device__ __forceinline__ void conv_stageB(char* smBp, const __nv_bfloat16* wsrc,
                                            int ldw, int tid)
{
    __syncthreads();
    for (int e = tid; e < 1024; e += 256) {
        int r = e >> 3, q = e & 7;
        uint4 v = *(const uint4*)(wsrc + (size_t)r * ldw + q * 8);
        *(uint4*)(smBp + SW128(r * 128 + q * 16)) = v;
    }
    __syncthreads();
}

// ---------------- implicit-GEMM 3x3 conv via HMMA, 3-term bf16 split ----------------
// Block: 128 x-pixels (one row y) x 128 couts; 8 warps (4M x 2N).
template<int CIN, int LAYER>
__global__ __launch_bounds__(256)
void conv_hmma_kernel(const float* __restrict__ bias)
{
    __shared__ __align__(128) __nv_bfloat16 smA[130 * 64];
    __shared__ __align__(128) __nv_bfloat16 smB[128 * 64];
    char* smAp = (char*)smA; char* smBp = (char*)smB;
    uint32_t smAb = smem_u32(smA), smBb = smem_u32(smB);

    const __nv_bfloat16* inh = (LAYER == 1) ? g_x1h : g_c1h;
    const __nv_bfloat16* inl = (LAYER == 1) ? g_x1l : g_c1l;
    const __nv_bfloat16* wh  = (LAYER == 1) ? g_wc1h : g_wc2h;
    const __nv_bfloat16* wl  = (LAYER == 1) ? g_wc1l : g_wc2l;
    uint32_t* outh = (uint32_t*)((LAYER == 1) ? g_c1h : g_c2h);
    uint32_t* outl = (uint32_t*)((LAYER == 1) ? g_c1l : g_c2l);

    const int tid = threadIdx.x, lane = tid & 31, wid = tid >> 5;
    const int warp_m = wid & 3, warp_n = wid >> 2;
    const int x0 = blockIdx.x * 128;
    const int y = blockIdx.y;
    const int b = blockIdx.z;

    float acc[2][8][4] = {};

    for (int cc = 0; cc < CIN / 64; cc++) {
        for (int ky = 0; ky < 3; ky++) {
            int gy = y + ky - 1;
            int rowok = ((unsigned)gy < 256u) ? 1 : 0;
            size_t rb = (((size_t)b * 256 + (rowok ? gy : 0)) * 256) * CIN + cc * 64;
            // term hh and hl share A_h
            conv_stageA(smAp, inh + rb, x0, rowok, CIN, tid);
            for (int kx = 0; kx < 3; kx++) {
                conv_stageB(smBp, wh + ((size_t)(ky * 3 + kx) * 128) * CIN + cc * 64, CIN, tid);
                mma_block_pass(smAb, smBb, kx, warp_m, warp_n, lane, acc);
            }
            for (int kx = 0; kx < 3; kx++) {
                conv_stageB(smBp, wl + ((size_t)(ky * 3 + kx) * 128) * CIN + cc * 64, CIN, tid);
                mma_block_pass(smAb, smBb, kx, warp_m, warp_n, lane, acc);
            }
            // term lh
            conv_stageA(smAp, inl + rb, x0, rowok, CIN, tid);
            for (int kx = 0; kx < 3; kx++) {
                conv_stageB(smBp, wh + ((size_t)(ky * 3 + kx) * 128) * CIN + cc * 64, CIN, tid);
                mma_block_pass(smAb, smBb, kx, warp_m, warp_n, lane, acc);
            }
        }
    }

    // epilogue: bias + relu -> split hi/lo -> channel-last [pixel][128]
    const int g = lane >> 2, t4 = lane & 3;
    size_t pixbase = ((size_t)b * 256 + y) * 256 + x0;
    #pragma unroll
    for (int i = 0; i < 2; i++) {
        size_t pA = pixbase + warp_m * 32 + i * 16 + g;
        size_t pB = pA + 8;
        #pragma unroll
        for (int j = 0; j < 8; j++) {
            int col = warp_n * 64 + j * 8 + t4 * 2;
            float b0 = bias[col], b1v = bias[col + 1];
            uint32_t uh, ul;
            float v0 = fmaxf(acc[i][j][0] + b0, 0.f);
            float v1 = fmaxf(acc[i][j][1] + b1v, 0.f);
            split2(v0, v1, uh, ul);
            outh[pA * 64 + (col >> 1)] = uh;
            outl[pA * 64 + (col >> 1)] = ul;
            float v2 = fmaxf(acc[i][j][2] + b0, 0.f);
            float v3 = fmaxf(acc[i][j][3] + b1v, 0.f);
            split2(v2, v3, uh, ul);
            outh[pB * 64 + (col >> 1)] = uh;
            outl[pB * 64 + (col >> 1)] = ul;
        }
    }
}

// ---------------- fc-style GEMM staging chunk (validated R6 core) ----------------
__device__ __forceinline__ void gemm_chunk(
    char* smAp, char* smBp, uint32_t smAb, uint32_t smBb,
    const __nv_bfloat16* __restrict__ Ag, int lda, int m0,
    const __nv_bfloat16* __restrict__ Bg, int ldb, int n0, int koff,
    int tid, int warp_m, int warp_n, int lane,
    float acc[2][8][4])
{
    __syncthreads();
    for (int e = tid; e < 1024; e += 256) {
        int row = e >> 3, uc = e & 7;
        int grow = m0 + row;
        uint4 v = make_uint4(0, 0, 0, 0);
        if (grow < NPTS)
            v = *(const uint4*)(Ag + (size_t)grow * lda + koff + uc * 8);
        *(uint4*)(smAp + SW128(row * 128 + uc * 16)) = v;
    }
    for (int e = tid; e < 1024; e += 256) {
        int row = e >> 3, uc = e & 7;
        uint4 v = *(const uint4*)(Bg + (size_t)(n0 + row) * ldb + koff + uc * 8);
        *(uint4*)(smBp + SW128(row * 128 + uc * 16)) = v;
    }
    __syncthreads();
    mma_block_pass(smAb, smBb, 0, warp_m, warp_n, lane, acc);
}

// ---------------- fuse1x1: acc = x_ac @ Wx (3-term); out = relu_conv2 + acc + b1x1 ----------------
__global__ __launch_bounds__(256)
void fuse1x1_kernel(const float* __restrict__ bx)
{
    __shared__ __align__(128) __nv_bfloat16 smA[128 * 64];
    __shared__ __align__(128) __nv_bfloat16 smB[128 * 64];
    char* smAp = (char*)smA; char* smBp = (char*)smB;
    uint32_t smAb = smem_u32(smA), smBb = smem_u32(smB);

    const int tid = threadIdx.x, lane = tid & 31, wid = tid >> 5;
    const int warp_m = wid & 3, warp_n = wid >> 2;
    const int m0 = blockIdx.x * 128;

    float acc[2][8][4] = {};
    const __nv_bfloat16* Aph[3] = {g_xah, g_xal, g_xah};
    const __nv_bfloat16* Bph[3] = {g_wxh, g_wxh, g_wxl};
    for (int ph = 0; ph < 3; ph++)
        gemm_chunk(smAp, smBp, smAb, smBb, Aph[ph], 64, m0,
                   Bph[ph], 64, 0, 0, tid, warp_m, warp_n, lane, acc);

    const uint32_t* c2h = (const uint32_t*)g_c2h;
    const uint32_t* c2l = (const uint32_t*)g_c2l;
    const int g = lane >> 2, t4 = lane & 3;
    #pragma unroll
    for (int i = 0; i < 2; i++) {
        size_t pA = (size_t)m0 + warp_m * 32 + i * 16 + g;
        size_t pB = pA + 8;
        #pragma unroll
        for (int j = 0; j < 8; j++) {
            int col = warp_n * 64 + j * 8 + t4 * 2;
            float bb0 = bx[col], bb1 = bx[col + 1];
            uint32_t ph = c2h[pA * 64 + (col >> 1)], pl = c2l[pA * 64 + (col >> 1)];
            float f0 = bf2f_lo(ph) + bf2f_lo(pl);
            float f1 = bf2f_hi(ph) + bf2f_hi(pl);
            *(float2*)&g_xat[pA * 128 + col] =
                make_float2(acc[i][j][0] + bb0 + f0, acc[i][j][1] + bb1 + f1);
            uint32_t qh = c2h[pB * 64 + (col >> 1)], ql = c2l[pB * 64 + (col >> 1)];
            float f2 = bf2f_lo(qh) + bf2f_lo(ql);
            float f3 = bf2f_hi(qh) + bf2f_hi(ql);
            *(float2*)&g_xat[pB * 128 + col] =
                make_float2(acc[i][j][2] + bb0 + f2, acc[i][j][3] + bb1 + f3);
        }
    }
}

// ---------------- g_xat [b][y][x][c] -> x_after NCHW fp32 ----------------
__global__ void xat2nchw_kernel(float* __restrict__ dst)
{
    __shared__ float s[32 * 33];
    int tid = threadIdx.x;
    int x0 = blockIdx.x * 32, y = blockIdx.y;
    int b = blockIdx.z >> 2, c0 = (blockIdx.z & 3) * 32;
    #pragma unroll
    for (int i = 0; i < 4; i++) {
        int lin = tid + i * 256;
        int c = lin & 31, x = lin >> 5;
        s[x * 33 + c] = g_xat[(((size_t)b * 256 + y) * 256 + x0 + x) * 128 + c0 + c];
    }
    __syncthreads();
    #pragma unroll
    for (int i = 0; i < 4; i++) {
        int lin = tid + i * 256;
        int x = lin & 31, c = lin >> 5;
        dst[(((size_t)b * 128 + c0 + c) * 256 + y) * 256 + x0 + x] = s[x * 33 + c];
    }
}

// ---------------- bilinear sampling (reads g_xat fp32) ----------------
__global__ void sample_kernel(const float* __restrict__ p)
{
    int gid  = blockIdx.x * blockDim.x + threadIdx.x;
    int wid  = gid >> 5;
    int lane = gid & 31;
    if (wid >= NPTS) return;
    int b = (wid >= N_) ? 1 : 0;

    float sx = p[(size_t)wid * 3 + 0];
    float sy = p[(size_t)wid * 3 + 1];
    float px = fminf(fmaxf(sx * 255.f, 0.f), 255.f);
    float py = fminf(fmaxf(sy * 255.f, 0.f), 255.f);
    float x0f = floorf(px), y0f = floorf(py);
    int x0 = (int)x0f, y0 = (int)y0f;
    int x1 = min(x0 + 1, 255), y1 = min(y0 + 1, 255);
    float wx = px - x0f, wy = py - y0f;
    float w00 = (1.f - wx) * (1.f - wy);
    float w01 = wx * (1.f - wy);
    float w10 = (1.f - wx) * wy;
    float w11 = wx * wy;

    const float4* F = (const float4*)g_xat;
    size_t r00 = ((size_t)(b * 256 + y0) * 256 + x0) * 32 + lane;
    size_t r01 = ((size_t)(b * 256 + y0) * 256 + x1) * 32 + lane;
    size_t r10 = ((size_t)(b * 256 + y1) * 256 + x0) * 32 + lane;
    size_t r11 = ((size_t)(b * 256 + y1) * 256 + x1) * 32 + lane;
    float4 f00 = F[r00], f01 = F[r01], f10 = F[r10], f11 = F[r11];
    float4 r;
    r.x = f00.x * w00 + f01.x * w01 + f10.x * w10 + f11.x * w11;
    r.y = f00.y * w00 + f01.y * w01 + f10.y * w10 + f11.y * w11;
    r.z = f00.z * w00 + f01.z * w01 + f10.z * w10 + f11.z * w11;
    r.w = f00.w * w00 + f01.w * w01 + f10.w * w10 + f11.w * w11;

    uint32_t h0, l0, h1, l1;
    split2(r.x, r.y, h0, l0);
    split2(r.z, r.w, h1, l1);
    uint32_t* ch = (uint32_t*)g_c0h;
    uint32_t* cl = (uint32_t*)g_c0l;
    size_t base = (size_t)wid * 64 + lane * 2;
    ch[base] = h0; ch[base + 1] = h1;
    cl[base] = l0; cl[base + 1] = l1;

    if (lane == 0) {
        int ix = min(max((int)(sx * 256.f), 0), 255);
        int iy = min(max((int)(sy * 256.f), 0), 255);
        int idx = ix + (iy << 8);
        g_idx[wid] = idx;
        atomicAdd(&g_cnt[b * RES2 + idx], 1.f);
    }
}

// ---------------- fc1: t = relu(c0 @ W1 + b1), 3-term bf16 split ----------------
__global__ __launch_bounds__(256)
void fc1_hmma_kernel(const float* __restrict__ bias)
{
    __shared__ __align__(128) __nv_bfloat16 smA[128 * 64];
    __shared__ __align__(128) __nv_bfloat16 smB[128 * 64];
    char* smAp = (char*)smA; char* smBp = (char*)smB;
    uint32_t smAb = smem_u32(smA), smBb = smem_u32(smB);

    const int tid = threadIdx.x, lane = tid & 31, wid = tid >> 5;
    const int warp_m = wid & 3, warp_n = wid >> 2;
    const int m0 = blockIdx.x * 128, n0 = blockIdx.y * 128;

    float acc[2][8][4] = {};
    const __nv_bfloat16* Aph[3] = {g_c0h, g_c0l, g_c0h};
    const __nv_bfloat16* Bph[3] = {g_w1t_h, g_w1t_h, g_w1t_l};
    for (int ph = 0; ph < 3; ph++)
        for (int kc = 0; kc < 2; kc++)
            gemm_chunk(smAp, smBp, smAb, smBb, Aph[ph], 128, m0,
                       Bph[ph], 128, n0, kc * 64, tid, warp_m, warp_n, lane, acc);

    uint32_t* th = (uint32_t*)g_th;
    uint32_t* tl = (uint32_t*)g_tl;
    const int g = lane >> 2, t4 = lane & 3;
    #pragma unroll
    for (int i = 0; i < 2; i++) {
        int rowA = m0 + warp_m * 32 + i * 16 + g;
        int rowB = rowA + 8;
        #pragma unroll
        for (int j = 0; j < 8; j++) {
            int col = n0 + warp_n * 64 + j * 8 + t4 * 2;
            float b0 = bias[col], b1 = bias[col + 1];
            if (rowA < NPTS) {
                float v0 = fmaxf(acc[i][j][0] + b0, 0.f);
                float v1 = fmaxf(acc[i][j][1] + b1, 0.f);
                uint32_t uh, ul; split2(v0, v1, uh, ul);
                size_t o = (size_t)rowA * 128 + (col >> 1);
                th[o] = uh; tl[o] = ul;
            }
            if (rowB < NPTS) {
                float v2 = fmaxf(acc[i][j][2] + b0, 0.f);
                float v3 = fmaxf(acc[i][j][3] + b1, 0.f);
                uint32_t uh, ul; split2(v2, v3, uh, ul);
                size_t o = (size_t)rowB * 128 + (col >> 1);
                th[o] = uh; tl[o] = ul;
            }
        }
    }
}

// ---------------- fc2: c = t@W2 + b2 + c_last@Wc + bc; write c; scatter-add ----------------
__global__ __launch_bounds__(256)
void fc2_hmma_kernel(const float* __restrict__ b2, const float* __restrict__ bc,
                     float* __restrict__ outc)
{
    __shared__ __align__(128) __nv_bfloat16 smA[128 * 64];
    __shared__ __align__(128) __nv_bfloat16 smB[128 * 64];
    char* smAp = (char*)smA; char* smBp = (char*)smB;
    uint32_t smAb = smem_u32(smA), smBb = smem_u32(smB);

    const int tid = threadIdx.x, lane = tid & 31, wid = tid >> 5;
    const int warp_m = wid & 3, warp_n = wid >> 2;
    const int m0 = blockIdx.x * 128;

    float acc[2][8][4] = {};
    const __nv_bfloat16* Aph[6] = {g_th, g_tl, g_th, g_clh, g_cll, g_clh};
    const __nv_bfloat16* Bph[6] = {g_w2t_h, g_w2t_h, g_w2t_l, g_wct_h, g_wct_h, g_wct_l};
    const int ldp[6] = {256, 256, 256, 64, 64, 64};
    const int ncp[6] = {4, 4, 4, 1, 1, 1};
    for (int ph = 0; ph < 6; ph++)
        for (int kc = 0; kc < ncp[ph]; kc++)
            gemm_chunk(smAp, smBp, smAb, smBb, Aph[ph], ldp[ph], m0,
                       Bph[ph], ldp[ph], 0, kc * 64, tid, warp_m, warp_n, lane, acc);

    const int g = lane >> 2, t4 = lane & 3;
    int rows[4], idxs[4], bbs[4];
    #pragma unroll
    for (int i = 0; i < 2; i++) {
        rows[i * 2]     = m0 + warp_m * 32 + i * 16 + g;
        rows[i * 2 + 1] = rows[i * 2] + 8;
    }
    #pragma unroll
    for (int k = 0; k < 4; k++) {
        idxs[k] = 0; bbs[k] = 0;
        if (rows[k] < NPTS) { idxs[k] = g_idx[rows[k]]; bbs[k] = (rows[k] >= N_) ? 1 : 0; }
    }
    #pragma unroll
    for (int i = 0; i < 2; i++) {
        #pragma unroll
        for (int j = 0; j < 8; j++) {
            int col = warp_n * 64 + j * 8 + t4 * 2;
            float bb0 = b2[col] + bc[col], bb1 = b2[col + 1] + bc[col + 1];
            int rA = rows[i * 2], rB = rows[i * 2 + 1];
            float v0 = acc[i][j][0] + bb0, v1 = acc[i][j][1] + bb1;
            float v2 = acc[i][j][2] + bb0, v3 = acc[i][j][3] + bb1;
            if (rA < NPTS) {
                *(float2*)(outc + (size_t)rA * 128 + col) = make_float2(v0, v1);
                int ia = idxs[i * 2], ba = bbs[i * 2];
                atomicAdd(&g_sums[((size_t)(ba * 128 + col)) * RES2 + ia], v0);
                atomicAdd(&g_sums[((size_t)(ba * 128 + col + 1)) * RES2 + ia], v1);
            }
            if (rB < NPTS) {
                *(float2*)(outc + (size_t)rB * 128 + col) = make_float2(v2, v3);
                int ib = idxs[i * 2 + 1], bbx = bbs[i * 2 + 1];
                atomicAdd(&g_sums[((size_t)(bbx * 128 + col)) * RES2 + ib], v2);
                atomicAdd(&g_sums[((size_t)(bbx * 128 + col + 1)) * RES2 + ib], v3);
            }
        }
    }
}

// ---------------- plane finalize + maxpool ----------------
__global__ void plane_kernel(float* __restrict__ dout)
{
    int i = blockIdx.x * blockDim.x + threadIdx.x;
    if (i >= B_ * 128 * RES2) return;
    int b = i >> 23;
    int idx = i & 65535;
    float cnt = g_cnt[(b << 16) + idx];
    dout[BP_OFF + i] = g_sums[i] / fmaxf(cnt, 1.f);
}

__global__ void pool_kernel(float* __restrict__ dout)
{
    int i = blockIdx.x * blockDim.x + threadIdx.x;
    if (i >= B_ * 128 * 128 * 128) return;
    int px = i & 127, py = (i >> 7) & 127, bc = i >> 14;
    const float* pl = dout + BP_OFF + (size_t)bc * RES2;
    int r0 = (py * 2) * 256 + px * 2;
    float v = fmaxf(fmaxf(pl[r0], pl[r0 + 1]), fmaxf(pl[r0 + 256], pl[r0 + 257]));
    dout[OUT_OFF + i] = v;
}

// ---------------- launch ----------------
extern "C" void kernel_launch(void* const* d_in, const int* in_sizes, int n_in,
                              void* d_out, int out_size)
{
    const float* p     = (const float*)d_in[0];
    const float* x_xy  = (const float*)d_in[1];
    const float* x_ac  = (const float*)d_in[2];
    const float* clast = (const float*)d_in[3];
    const float* w1    = (const float*)d_in[4];
    const float* bb1   = (const float*)d_in[5];
    const float* w2    = (const float*)d_in[6];
    const float* bb2   = (const float*)d_in[7];
    const float* w1x1  = (const float*)d_in[8];
    const float* b1x1  = (const float*)d_in[9];
    const float* wfc1  = (const float*)d_in[10];
    const float* bfc1  = (const float*)d_in[11];
    const float* wfc2  = (const float*)d_in[12];
    const float* bfc2  = (const float*)d_in[13];
    const float* wfcc  = (const float*)d_in[14];
    const float* bfcc  = (const float*)d_in[15];
    float* out = (float*)d_out;

    zero_kernel<<<2048, 256>>>();
    wconv_kernel<<<576, 256>>>(wfc1, wfc2, wfcc, w1, w2, w1x1);
    clconv_kernel<<<(NPTS * 32 + 255) / 256, 256>>>(clast);
    cvt_kernel<<<dim3(4, 256, 2), 256>>>(x_xy, 0);
    cvt_kernel<<<dim3(4, 256, 2), 256>>>(x_ac, 1);
    conv_hmma_kernel<64, 1><<<dim3(2, 256, 2), 256>>>(bb1);
    conv_hmma_kernel<128, 2><<<dim3(2, 256, 2), 256>>>(bb2);
    fuse1x1_kernel<<<NPIX / 128, 256>>>(b1x1);
    xat2nchw_kernel<<<dim3(8, 256, 8), 256>>>(out + XA_OFF);
    sample_kernel<<<(NPTS * 32 + 255) / 256, 256>>>(p);
    fc1_hmma_kernel<<<dim3(MTILES, 2), 256>>>(bfc1);
    fc2_hmma_kernel<<<dim3(MTILES, 1), 256>>>(bfc2, bfcc, out + C_OFF);
    plane_kernel<<<(B_ * 128 * RES2) / 256, 256>>>(out);
    pool_kernel<<<(B_ * 128 * 128 * 128) / 256, 256>>>(out);
}